// round 14
// baseline (speedup 1.0000x reference)
#include <cuda_runtime.h>
#include <cuda_fp16.h>
#include <cstdint>

#define NPTS 65536
#define DIM  256
#define KCB  4096

#define BM      128
#define NGROUP  128                    // codewords per chunk
#define NCHUNK  16                     // chunks per unit (half codebook)
#define NUNITS  1024                   // (row-tile, codebook-half) pairs
#define NTHREADS 256                   // 8 warps

// smem byte offsets (192 KB + tail)
#define A_H 0
#define B_0 65536
#define B_1 131072
#define S_UNIT 196608                  // int: current work unit
#define SMEM_TOTAL (196608 + 128)

// ---------------- device scratch (allocation-free rule) ----------------
__device__ float g_xsq[NPTS];
__device__ float g_csq[KCB];
__device__ __half g_xh[(size_t)NPTS * DIM];
__device__ __half g_ch[(size_t)KCB * DIM];
__device__ float g_cval[NPTS][32];
__device__ int   g_cand[NPTS][32];
__device__ int   g_work;

// ---------------- helpers ----------------
__device__ __forceinline__ uint32_t smem_u32(const void* p) {
    uint32_t a;
    asm("{ .reg .u64 t; cvta.to.shared.u64 t, %1; cvt.u32.u64 %0, t; }"
        : "=r"(a) : "l"(p));
    return a;
}
// rows have 512B pitch (32 x 16B units); swizzle permutes units within each
// 128B block by row&7 -> conflict-free ldmatrix and stores.
__device__ __forceinline__ uint32_t swz_off(uint32_t r, uint32_t u) {
    return r * 512u + (((u) & ~7u) | (((u) ^ (r)) & 7u)) * 16u;
}

#define LDSM4(r0, r1, r2, r3, addr)                                             \
    asm volatile("ldmatrix.sync.aligned.m8n8.x4.shared.b16 {%0,%1,%2,%3}, [%4];" \
                 : "=r"(r0), "=r"(r1), "=r"(r2), "=r"(r3) : "r"(addr))

#define MMA16816(d, a0, a1, a2, a3, b0, b1)                                     \
    asm volatile("mma.sync.aligned.m16n8k16.row.col.f32.f16.f16.f32 "          \
                 "{%0,%1,%2,%3}, {%4,%5,%6,%7}, {%8,%9}, {%0,%1,%2,%3};"       \
                 : "+f"((d)[0]), "+f"((d)[1]), "+f"((d)[2]), "+f"((d)[3])       \
                 : "r"(a0), "r"(a1), "r"(a2), "r"(a3), "r"(b0), "r"(b1))

#define CP16(sdst, gsrc)                                                        \
    asm volatile("cp.async.cg.shared.global [%0], [%1], 16;"                    \
                 :: "r"(sdst), "l"(gsrc) : "memory")
#define CP_COMMIT() asm volatile("cp.async.commit_group;" ::: "memory")
#define CP_WAIT1()  asm volatile("cp.async.wait_group 1;" ::: "memory")
#define CP_WAIT0()  asm volatile("cp.async.wait_group 0;" ::: "memory")

// Fold chunk cc's scores (accumulator set accp) into the per-row top-2.
// Register-only w.r.t. acc; placed inside the NEXT chunk's MMA stream so it
// executes in tensor-pipe structural-stall slots.
#define FOLD_CHUNK(accp, cc)                                                    \
    {                                                                           \
        int colb_ = cw0 + (cc) * NGROUP + wn * 64 + (lane & 3) * 2;             \
        _Pragma("unroll")                                                       \
        for (int j_ = 0; j_ < 8; j_++) {                                        \
            int col_ = colb_ + j_ * 8;                                          \
            float cs0_ = __ldg(&g_csq[col_]);                                   \
            float cs1_ = __ldg(&g_csq[col_ + 1]);                               \
            _Pragma("unroll")                                                   \
            for (int t_ = 0; t_ < 2; t_++) {                                    \
                _Pragma("unroll")                                               \
                for (int s_ = 0; s_ < 2; s_++) {                                \
                    int ri_ = t_ * 2 + s_;                                      \
                    float s0_ = fmaf(-2.f, (accp)[t_][j_][s_ * 2 + 0],          \
                                     my_xsq[ri_]) + cs0_;                       \
                    float s1_ = fmaf(-2.f, (accp)[t_][j_][s_ * 2 + 1],          \
                                     my_xsq[ri_]) + cs1_;                       \
                    if (s0_ < v1[ri_]) { v2[ri_] = v1[ri_]; i2[ri_] = i1[ri_];  \
                                         v1[ri_] = s0_; i1[ri_] = col_; }       \
                    else if (s0_ < v2[ri_]) { v2[ri_] = s0_; i2[ri_] = col_; }  \
                    if (s1_ < v1[ri_]) { v2[ri_] = v1[ri_]; i2[ri_] = i1[ri_];  \
                                         v1[ri_] = s1_; i1[ri_] = col_ + 1; }   \
                    else if (s1_ < v2[ri_]) { v2[ri_] = s1_; i2[ri_] = col_ + 1; } \
                }                                                               \
            }                                                                   \
        }                                                                       \
    }

// ---------------------------------------------------------------------------
// Prep (fused): fp16 round of x and codebook + row squared norms + counter
// reset. One warp per row; each lane owns 8 contiguous elements.
// ---------------------------------------------------------------------------
__global__ void prep_kernel(const float* __restrict__ x,
                            const float* __restrict__ cb) {
    if (blockIdx.x == 0 && threadIdx.x == 0) g_work = 0;

    int warp = (blockIdx.x * blockDim.x + threadIdx.x) >> 5;
    int lane = threadIdx.x & 31;
    const float* src;
    __half* dst;
    float* nrm;
    if (warp < NPTS) {
        src = x + (size_t)warp * DIM; dst = g_xh + (size_t)warp * DIM;
        nrm = g_xsq + warp;
    } else {
        int r = warp - NPTS;
        if (r >= KCB) return;
        src = cb + (size_t)r * DIM; dst = g_ch + (size_t)r * DIM;
        nrm = g_csq + r;
    }

    float4 a = *(const float4*)(src + lane * 8);
    float4 b = *(const float4*)(src + lane * 8 + 4);
    float f[8] = {a.x, a.y, a.z, a.w, b.x, b.y, b.z, b.w};
    __align__(16) __half h[8];
    float s = 0.f;
#pragma unroll
    for (int i = 0; i < 8; i++) {
        h[i] = __float2half_rn(f[i]);
        s = fmaf(f[i], f[i], s);
    }
    *(uint4*)(dst + lane * 8) = *(uint4*)h;
#pragma unroll
    for (int o = 16; o > 0; o >>= 1) s += __shfl_xor_sync(0xFFFFFFFFu, s, o);
    if (lane == 0) *nrm = s;
}

// ---------------------------------------------------------------------------
// Main: persistent-CTA fp16 mma.sync distance GEMM (Xh*Ch), per-row top-2
// candidate pool. Unit = (row-tile of 128, codebook half of 2048).
// 8 warps; warp (wm=wid&3, wn=wid>>2) owns a 32x64 score tile per chunk.
// Accumulators double-buffered: chunk c's fold overlaps chunk c+1's MMAs.
// ---------------------------------------------------------------------------
__global__ __launch_bounds__(NTHREADS, 1) void vq_mma_kernel() {
    extern __shared__ char smem[];
    const uint32_t sb = smem_u32(smem);

    const int tid = threadIdx.x;
    const int lane = tid & 31;
    const int wid = tid >> 5;
    const int wm = wid & 3;            // row group (32 rows)
    const int wn = wid >> 2;           // col group (64 cols)

    // ldmatrix lane->(row, k-unit) mappings
    const uint32_t ra = (lane & 7) + ((lane >> 3) & 1) * 8;   // A x4
    const uint32_t ua = (uint32_t)(lane >> 4);
    const uint32_t rb = (lane & 7) + (lane >> 4) * 8;         // B x4
    const uint32_t ub = (uint32_t)((lane >> 3) & 1);

    for (;;) {
        if (tid == 0) *(int*)(smem + S_UNIT) = atomicAdd(&g_work, 1);
        __syncthreads();
        const int unit = *(int*)(smem + S_UNIT);
        if (unit >= NUNITS) break;
        const int rowbase = (unit >> 1) * BM;
        const int khalf = unit & 1;
        const int cw0 = khalf * (KCB / 2);     // first codeword of this half
        __syncthreads();   // everyone read S_UNIT before reuse

        // Stage A (Xh): 128 rows x 32 units
#pragma unroll
        for (int i = 0; i < 16; i++) {
            int flat = tid + NTHREADS * i;
            int r = flat >> 5, u = flat & 31;
            *(uint4*)(smem + A_H + swz_off(r, u)) =
                *((const uint4*)(g_xh + (size_t)(rowbase + r) * DIM) + u);
        }

        // Prefetch chunks 0 and 1 (128 codewords each)
#pragma unroll
        for (int c = 0; c < 2; c++) {
            uint32_t boff = (c & 1) ? B_1 : B_0;
#pragma unroll
            for (int i = 0; i < 16; i++) {
                int flat = tid + NTHREADS * i;
                int r = flat >> 5, u = flat & 31;
                CP16(sb + boff + swz_off(r, u),
                     (const char*)(g_ch + (size_t)(cw0 + c * NGROUP + r) * DIM) + u * 16);
            }
            CP_COMMIT();
        }

        float my_xsq[4];
#pragma unroll
        for (int t = 0; t < 2; t++)
#pragma unroll
            for (int s = 0; s < 2; s++)
                my_xsq[t * 2 + s] =
                    g_xsq[rowbase + wm * 32 + t * 16 + (lane >> 2) + s * 8];

        float v1[4], v2[4];
        int i1[4], i2[4];
#pragma unroll
        for (int i = 0; i < 4; i++) {
            v1[i] = 3.4e38f; v2[i] = 3.4e38f; i1[i] = 0; i2[i] = 0;
        }

        float acc[2][2][8][4];             // [set][m-tile][n8-frag][frag]

        for (int c = 0; c < NCHUNK; c++) {
            if (c == NCHUNK - 1) CP_WAIT0(); else CP_WAIT1();
            __syncthreads();

            const int p = c & 1;
            const uint32_t boff = p ? B_1 : B_0;

#pragma unroll
            for (int t = 0; t < 2; t++)
#pragma unroll
                for (int j = 0; j < 8; j++)
#pragma unroll
                    for (int e = 0; e < 4; e++) acc[p][t][j][e] = 0.f;

            {
                const uint32_t ar0 = wm * 32 + ra;
                const uint32_t ar1 = wm * 32 + 16 + ra;
                const uint32_t br0 = wn * 64 + rb;
#pragma unroll
                for (int ks = 0; ks < 16; ks++) {
                    uint32_t au = ks * 2 + ua;
                    uint32_t bu = ks * 2 + ub;
                    uint32_t a0, a1, a2, a3, a4, a5, a6, a7;
                    uint32_t b[16];
                    LDSM4(a0, a1, a2, a3, sb + A_H + swz_off(ar0, au));
                    LDSM4(a4, a5, a6, a7, sb + A_H + swz_off(ar1, au));
                    LDSM4(b[0],  b[1],  b[2],  b[3],  sb + boff + swz_off(br0, bu));
                    LDSM4(b[4],  b[5],  b[6],  b[7],  sb + boff + swz_off(br0 + 16, bu));
                    LDSM4(b[8],  b[9],  b[10], b[11], sb + boff + swz_off(br0 + 32, bu));
                    LDSM4(b[12], b[13], b[14], b[15], sb + boff + swz_off(br0 + 48, bu));
#pragma unroll
                    for (int j = 0; j < 8; j++) {
                        MMA16816(acc[p][0][j], a0, a1, a2, a3, b[2 * j], b[2 * j + 1]);
                        MMA16816(acc[p][1][j], a4, a5, a6, a7, b[2 * j], b[2 * j + 1]);
                    }
                    // Fold of the PREVIOUS chunk rides in this chunk's
                    // tensor-pipe stall slots (register-only, independent).
                    if (ks == 0 && c > 0) FOLD_CHUNK(acc[p ^ 1], c - 1);
                }
            }

            __syncthreads();

            if (c + 2 < NCHUNK) {
                int nc = c + 2;
                uint32_t nboff = (nc & 1) ? B_1 : B_0;
#pragma unroll
                for (int i = 0; i < 16; i++) {
                    int flat = tid + NTHREADS * i;
                    int r = flat >> 5, u = flat & 31;
                    CP16(sb + nboff + swz_off(r, u),
                         (const char*)(g_ch + (size_t)(cw0 + nc * NGROUP + r) * DIM) + u * 16);
                }
                CP_COMMIT();
            }
        }

        // Fold the final chunk.
        FOLD_CHUNK(acc[(NCHUNK - 1) & 1], NCHUNK - 1);

        // Emit 16 candidates per row into this half's slot range
        // (8 owning threads x top-2, disjoint col sets; halves disjoint too).
#pragma unroll
        for (int t = 0; t < 2; t++)
#pragma unroll
            for (int s = 0; s < 2; s++) {
                int ri = t * 2 + s;
                int row = rowbase + wm * 32 + t * 16 + (lane >> 2) + s * 8;
                int slot = khalf * 16 + (wn * 4 + (lane & 3)) * 2;
                g_cval[row][slot] = v1[ri];      g_cand[row][slot] = i1[ri];
                g_cval[row][slot + 1] = v2[ri];  g_cand[row][slot + 1] = i2[ri];
            }
        __syncthreads();   // A/B reuse safety before next unit restages
    }
}

// ---------------------------------------------------------------------------
// Rescore: approx-top-4 of the 32 candidates, exact fp32 rescore, write
// index + gather. One warp per row.
// ---------------------------------------------------------------------------
__global__ void rescore_kernel(const float* __restrict__ x,
                               const float* __restrict__ cb,
                               float* __restrict__ out) {
    int row = (blockIdx.x * blockDim.x + threadIdx.x) >> 5;
    int lane = threadIdx.x & 31;
    if (row >= NPTS) return;

    float v = g_cval[row][lane];
    int ci = g_cand[row][lane];

    int cand[4];
#pragma unroll
    for (int r = 0; r < 4; r++) {
        float bv = v; int bi = ci;
#pragma unroll
        for (int o = 16; o > 0; o >>= 1) {
            float ov = __shfl_xor_sync(0xFFFFFFFFu, bv, o);
            int oi = __shfl_xor_sync(0xFFFFFFFFu, bi, o);
            if (ov < bv || (ov == bv && oi < bi)) { bv = ov; bi = oi; }
        }
        cand[r] = bi;
        if (ci == bi) v = 3.4e38f;    // indices unique across slots
    }

    const float4* xp = (const float4*)(x + (size_t)row * DIM);
    float4 xa = xp[lane * 2], xb = xp[lane * 2 + 1];
    float xsq = g_xsq[row];

    float best = 3.4e38f;
    int bi = KCB;
#pragma unroll
    for (int j = 0; j < 4; j++) {
        int cidx = cand[j];
        const float4* cp = (const float4*)(cb + (size_t)cidx * DIM);
        float4 ca = cp[lane * 2], cbv = cp[lane * 2 + 1];
        float d = 0.f;
        d = fmaf(xa.x, ca.x, d);  d = fmaf(xa.y, ca.y, d);
        d = fmaf(xa.z, ca.z, d);  d = fmaf(xa.w, ca.w, d);
        d = fmaf(xb.x, cbv.x, d); d = fmaf(xb.y, cbv.y, d);
        d = fmaf(xb.z, cbv.z, d); d = fmaf(xb.w, cbv.w, d);
#pragma unroll
        for (int o = 16; o > 0; o >>= 1) d += __shfl_xor_sync(0xFFFFFFFFu, d, o);
        float s = fmaf(-2.f, d, xsq) + g_csq[cidx];
        if (s < best || (s == best && cidx < bi)) { best = s; bi = cidx; }
    }

    if (lane == 0) out[(size_t)NPTS * DIM + row] = (float)bi;
    const float4* cp = (const float4*)(cb + (size_t)bi * DIM);
    float4* dst = (float4*)(out + (size_t)row * DIM);
    dst[lane * 2]     = cp[lane * 2];
    dst[lane * 2 + 1] = cp[lane * 2 + 1];
}

// ---------------------------------------------------------------------------
extern "C" void kernel_launch(void* const* d_in, const int* in_sizes, int n_in,
                              void* d_out, int out_size) {
    const float* x  = (const float*)d_in[0];   // (65536, 256) f32
    const float* cb = (const float*)d_in[1];   // (4096, 256)  f32
    float* out = (float*)d_out;

    int warps = NPTS + KCB;                    // one warp per row
    prep_kernel<<<(warps * 32 + 255) / 256, 256>>>(x, cb);

    cudaFuncSetAttribute(vq_mma_kernel,
                         cudaFuncAttributeMaxDynamicSharedMemorySize, SMEM_TOTAL);
    vq_mma_kernel<<<148, NTHREADS, SMEM_TOTAL>>>();

    rescore_kernel<<<NPTS / 8, 256>>>(x, cb, out);
}

// round 15
// speedup vs baseline: 1.3435x; 1.3435x over previous
#include <cuda_runtime.h>
#include <cuda_fp16.h>
#include <cstdint>

#define NPTS 65536
#define DIM  256
#define KCB  4096

#define BM      128
#define NGROUP  128                    // codewords per chunk
#define NCHUNK  16                     // chunks per unit (half codebook)
#define NUNITS  1024                   // (row-tile, codebook-half) pairs
#define NTHREADS 256                   // 8 warps

// smem byte offsets
#define A_H    0                       // 64 KB
#define B_0    65536                   // 64 KB
#define B_1    131072                  // 64 KB
#define CSQ_0  196608                  // 512 B
#define CSQ_1  197120                  // 512 B
#define S_UNIT 197632
#define SMEM_TOTAL 197760

// ---------------- device scratch (allocation-free rule) ----------------
__device__ float g_xsq[NPTS];
__device__ float g_csq[KCB];
__device__ __half g_xh[(size_t)NPTS * DIM];
__device__ __half g_ch[(size_t)KCB * DIM];
__device__ float g_cval[NPTS][32];
__device__ int   g_cand[NPTS][32];
__device__ int   g_work;

// ---------------- helpers ----------------
__device__ __forceinline__ uint32_t smem_u32(const void* p) {
    uint32_t a;
    asm("{ .reg .u64 t; cvta.to.shared.u64 t, %1; cvt.u32.u64 %0, t; }"
        : "=r"(a) : "l"(p));
    return a;
}
// rows have 512B pitch (32 x 16B units); swizzle permutes units within each
// 128B block by row&7 -> conflict-free ldmatrix and stores.
__device__ __forceinline__ uint32_t swz_off(uint32_t r, uint32_t u) {
    return r * 512u + (((u) & ~7u) | (((u) ^ (r)) & 7u)) * 16u;
}

#define LDSM4(r0, r1, r2, r3, addr)                                             \
    asm volatile("ldmatrix.sync.aligned.m8n8.x4.shared.b16 {%0,%1,%2,%3}, [%4];" \
                 : "=r"(r0), "=r"(r1), "=r"(r2), "=r"(r3) : "r"(addr))

#define MMA16816(d, a0, a1, a2, a3, b0, b1)                                     \
    asm volatile("mma.sync.aligned.m16n8k16.row.col.f32.f16.f16.f32 "          \
                 "{%0,%1,%2,%3}, {%4,%5,%6,%7}, {%8,%9}, {%0,%1,%2,%3};"       \
                 : "+f"((d)[0]), "+f"((d)[1]), "+f"((d)[2]), "+f"((d)[3])       \
                 : "r"(a0), "r"(a1), "r"(a2), "r"(a3), "r"(b0), "r"(b1))

#define CP16(sdst, gsrc)                                                        \
    asm volatile("cp.async.cg.shared.global [%0], [%1], 16;"                    \
                 :: "r"(sdst), "l"(gsrc) : "memory")
#define CP_COMMIT() asm volatile("cp.async.commit_group;" ::: "memory")
#define CP_WAIT1()  asm volatile("cp.async.wait_group 1;" ::: "memory")
#define CP_WAIT0()  asm volatile("cp.async.wait_group 0;" ::: "memory")

// ---------------------------------------------------------------------------
// Prep (fused): fp16 round of x and codebook + row squared norms + counter
// reset. One warp per row; each lane owns 8 contiguous elements.
// ---------------------------------------------------------------------------
__global__ void prep_kernel(const float* __restrict__ x,
                            const float* __restrict__ cb) {
    if (blockIdx.x == 0 && threadIdx.x == 0) g_work = 0;

    int warp = (blockIdx.x * blockDim.x + threadIdx.x) >> 5;
    int lane = threadIdx.x & 31;
    const float* src;
    __half* dst;
    float* nrm;
    if (warp < NPTS) {
        src = x + (size_t)warp * DIM; dst = g_xh + (size_t)warp * DIM;
        nrm = g_xsq + warp;
    } else {
        int r = warp - NPTS;
        if (r >= KCB) return;
        src = cb + (size_t)r * DIM; dst = g_ch + (size_t)r * DIM;
        nrm = g_csq + r;
    }

    float4 a = *(const float4*)(src + lane * 8);
    float4 b = *(const float4*)(src + lane * 8 + 4);
    float f[8] = {a.x, a.y, a.z, a.w, b.x, b.y, b.z, b.w};
    __align__(16) __half h[8];
    float s = 0.f;
#pragma unroll
    for (int i = 0; i < 8; i++) {
        h[i] = __float2half_rn(f[i]);
        s = fmaf(f[i], f[i], s);
    }
    *(uint4*)(dst + lane * 8) = *(uint4*)h;
#pragma unroll
    for (int o = 16; o > 0; o >>= 1) s += __shfl_xor_sync(0xFFFFFFFFu, s, o);
    if (lane == 0) *nrm = s;
}

// ---------------------------------------------------------------------------
// Main: persistent-CTA fp16 mma.sync distance GEMM (Xh*Ch), per-row top-2
// candidate pool. Unit = (row-tile of 128, codebook half of 2048).
// 8 warps; warp (wm=wid&3, wn=wid>>2) owns a 32x64 score tile per chunk.
// Pool stores RELATIVE scores (csq - 2*dot): per-row ranking identical since
// xsq is a per-row constant; the exact rescore re-adds it.
// ---------------------------------------------------------------------------
__global__ __launch_bounds__(NTHREADS, 1) void vq_mma_kernel() {
    extern __shared__ char smem[];
    const uint32_t sb = smem_u32(smem);

    const int tid = threadIdx.x;
    const int lane = tid & 31;
    const int wid = tid >> 5;
    const int wm = wid & 3;            // row group (32 rows)
    const int wn = wid >> 2;           // col group (64 cols)

    // ldmatrix lane->(row, k-unit) mappings
    const uint32_t ra = (lane & 7) + ((lane >> 3) & 1) * 8;   // A x4
    const uint32_t ua = (uint32_t)(lane >> 4);
    const uint32_t rb = (lane & 7) + (lane >> 4) * 8;         // B x4
    const uint32_t ub = (uint32_t)((lane >> 3) & 1);

    for (;;) {
        if (tid == 0) *(int*)(smem + S_UNIT) = atomicAdd(&g_work, 1);
        __syncthreads();
        const int unit = *(int*)(smem + S_UNIT);
        if (unit >= NUNITS) break;
        const int rowbase = (unit >> 1) * BM;
        const int khalf = unit & 1;
        const int cw0 = khalf * (KCB / 2);     // first codeword of this half
        __syncthreads();   // everyone read S_UNIT before reuse

        // Stage A (Xh): 128 rows x 32 units
#pragma unroll
        for (int i = 0; i < 16; i++) {
            int flat = tid + NTHREADS * i;
            int r = flat >> 5, u = flat & 31;
            *(uint4*)(smem + A_H + swz_off(r, u)) =
                *((const uint4*)(g_xh + (size_t)(rowbase + r) * DIM) + u);
        }

        // Prefetch chunks 0 and 1 (128 codewords each) + their csq slices
#pragma unroll
        for (int c = 0; c < 2; c++) {
            uint32_t boff = (c & 1) ? B_1 : B_0;
            uint32_t qoff = (c & 1) ? CSQ_1 : CSQ_0;
#pragma unroll
            for (int i = 0; i < 16; i++) {
                int flat = tid + NTHREADS * i;
                int r = flat >> 5, u = flat & 31;
                CP16(sb + boff + swz_off(r, u),
                     (const char*)(g_ch + (size_t)(cw0 + c * NGROUP + r) * DIM) + u * 16);
            }
            if (tid < 32)
                CP16(sb + qoff + tid * 16,
                     (const char*)(g_csq + cw0 + c * NGROUP) + tid * 16);
            CP_COMMIT();
        }

        float v1[4], v2[4];
        int i1[4], i2[4];
#pragma unroll
        for (int i = 0; i < 4; i++) {
            v1[i] = 3.4e38f; v2[i] = 3.4e38f; i1[i] = 0; i2[i] = 0;
        }

        float acc[2][8][4];                // [m-tile][n8-frag][frag]

        for (int c = 0; c < NCHUNK; c++) {
            // Zero acc while the cp.async wait drains
#pragma unroll
            for (int t = 0; t < 2; t++)
#pragma unroll
                for (int j = 0; j < 8; j++)
#pragma unroll
                    for (int e = 0; e < 4; e++) acc[t][j][e] = 0.f;

            if (c == NCHUNK - 1) CP_WAIT0(); else CP_WAIT1();
            __syncthreads();

            const uint32_t boff = (c & 1) ? B_1 : B_0;
            const uint32_t qoff = (c & 1) ? CSQ_1 : CSQ_0;

            {
                const uint32_t ar0 = wm * 32 + ra;
                const uint32_t ar1 = wm * 32 + 16 + ra;
                const uint32_t br0 = wn * 64 + rb;
#pragma unroll
                for (int ks = 0; ks < 16; ks++) {
                    uint32_t au = ks * 2 + ua;
                    uint32_t bu = ks * 2 + ub;
                    uint32_t a0, a1, a2, a3, a4, a5, a6, a7;
                    uint32_t b[16];
                    LDSM4(a0, a1, a2, a3, sb + A_H + swz_off(ar0, au));
                    LDSM4(a4, a5, a6, a7, sb + A_H + swz_off(ar1, au));
                    LDSM4(b[0],  b[1],  b[2],  b[3],  sb + boff + swz_off(br0, bu));
                    LDSM4(b[4],  b[5],  b[6],  b[7],  sb + boff + swz_off(br0 + 16, bu));
                    LDSM4(b[8],  b[9],  b[10], b[11], sb + boff + swz_off(br0 + 32, bu));
                    LDSM4(b[12], b[13], b[14], b[15], sb + boff + swz_off(br0 + 48, bu));
#pragma unroll
                    for (int j = 0; j < 8; j++) {
                        MMA16816(acc[0][j], a0, a1, a2, a3, b[2 * j], b[2 * j + 1]);
                        MMA16816(acc[1][j], a4, a5, a6, a7, b[2 * j], b[2 * j + 1]);
                    }
                }
            }

            // Fold chunk c scores (relative: cs - 2*dot) into per-row top-2.
            // csq read from smem (broadcast LDS.64 within each lane quad).
#pragma unroll
            for (int j = 0; j < 8; j++) {
                int cl = wn * 64 + j * 8 + (lane & 3) * 2;   // col within chunk
                float2 cs = *(const float2*)(smem + qoff + cl * 4);
                int col = cw0 + c * NGROUP + cl;
#pragma unroll
                for (int t = 0; t < 2; t++)
#pragma unroll
                    for (int s = 0; s < 2; s++) {
                        int ri = t * 2 + s;
                        float s0 = fmaf(-2.f, acc[t][j][s * 2 + 0], cs.x);
                        float s1 = fmaf(-2.f, acc[t][j][s * 2 + 1], cs.y);
                        if (s0 < v1[ri]) { v2[ri] = v1[ri]; i2[ri] = i1[ri];
                                           v1[ri] = s0; i1[ri] = col; }
                        else if (s0 < v2[ri]) { v2[ri] = s0; i2[ri] = col; }
                        if (s1 < v1[ri]) { v2[ri] = v1[ri]; i2[ri] = i1[ri];
                                           v1[ri] = s1; i1[ri] = col + 1; }
                        else if (s1 < v2[ri]) { v2[ri] = s1; i2[ri] = col + 1; }
                    }
            }

            __syncthreads();

            if (c + 2 < NCHUNK) {
                int nc = c + 2;
                uint32_t nboff = (nc & 1) ? B_1 : B_0;
                uint32_t nqoff = (nc & 1) ? CSQ_1 : CSQ_0;
#pragma unroll
                for (int i = 0; i < 16; i++) {
                    int flat = tid + NTHREADS * i;
                    int r = flat >> 5, u = flat & 31;
                    CP16(sb + nboff + swz_off(r, u),
                         (const char*)(g_ch + (size_t)(cw0 + nc * NGROUP + r) * DIM) + u * 16);
                }
                if (tid < 32)
                    CP16(sb + nqoff + tid * 16,
                         (const char*)(g_csq + cw0 + nc * NGROUP) + tid * 16);
                CP_COMMIT();
            }
        }

        // Emit 16 candidates per row into this half's slot range
        // (8 owning threads x top-2, disjoint col sets; halves disjoint too).
#pragma unroll
        for (int t = 0; t < 2; t++)
#pragma unroll
            for (int s = 0; s < 2; s++) {
                int ri = t * 2 + s;
                int row = rowbase + wm * 32 + t * 16 + (lane >> 2) + s * 8;
                int slot = khalf * 16 + (wn * 4 + (lane & 3)) * 2;
                g_cval[row][slot] = v1[ri];      g_cand[row][slot] = i1[ri];
                g_cval[row][slot + 1] = v2[ri];  g_cand[row][slot + 1] = i2[ri];
            }
        __syncthreads();   // A/B reuse safety before next unit restages
    }
}

// ---------------------------------------------------------------------------
// Rescore: approx-top-4 of the 32 candidates (ranked by relative scores),
// exact fp32 rescore with the reference formula + first-index tie-break,
// write index + gather. One warp per row.
// ---------------------------------------------------------------------------
__global__ void rescore_kernel(const float* __restrict__ x,
                               const float* __restrict__ cb,
                               float* __restrict__ out) {
    int row = (blockIdx.x * blockDim.x + threadIdx.x) >> 5;
    int lane = threadIdx.x & 31;
    if (row >= NPTS) return;

    float v = g_cval[row][lane];
    int ci = g_cand[row][lane];

    int cand[4];
#pragma unroll
    for (int r = 0; r < 4; r++) {
        float bv = v; int bi = ci;
#pragma unroll
        for (int o = 16; o > 0; o >>= 1) {
            float ov = __shfl_xor_sync(0xFFFFFFFFu, bv, o);
            int oi = __shfl_xor_sync(0xFFFFFFFFu, bi, o);
            if (ov < bv || (ov == bv && oi < bi)) { bv = ov; bi = oi; }
        }
        cand[r] = bi;
        if (ci == bi) v = 3.4e38f;    // indices unique across slots
    }

    const float4* xp = (const float4*)(x + (size_t)row * DIM);
    float4 xa = xp[lane * 2], xb = xp[lane * 2 + 1];
    float xsq = g_xsq[row];

    float best = 3.4e38f;
    int bi = KCB;
#pragma unroll
    for (int j = 0; j < 4; j++) {
        int cidx = cand[j];
        const float4* cp = (const float4*)(cb + (size_t)cidx * DIM);
        float4 ca = cp[lane * 2], cbv = cp[lane * 2 + 1];
        float d = 0.f;
        d = fmaf(xa.x, ca.x, d);  d = fmaf(xa.y, ca.y, d);
        d = fmaf(xa.z, ca.z, d);  d = fmaf(xa.w, ca.w, d);
        d = fmaf(xb.x, cbv.x, d); d = fmaf(xb.y, cbv.y, d);
        d = fmaf(xb.z, cbv.z, d); d = fmaf(xb.w, cbv.w, d);
#pragma unroll
        for (int o = 16; o > 0; o >>= 1) d += __shfl_xor_sync(0xFFFFFFFFu, d, o);
        float s = fmaf(-2.f, d, xsq) + g_csq[cidx];
        if (s < best || (s == best && cidx < bi)) { best = s; bi = cidx; }
    }

    if (lane == 0) out[(size_t)NPTS * DIM + row] = (float)bi;
    const float4* cp = (const float4*)(cb + (size_t)bi * DIM);
    float4* dst = (float4*)(out + (size_t)row * DIM);
    dst[lane * 2]     = cp[lane * 2];
    dst[lane * 2 + 1] = cp[lane * 2 + 1];
}

// ---------------------------------------------------------------------------
extern "C" void kernel_launch(void* const* d_in, const int* in_sizes, int n_in,
                              void* d_out, int out_size) {
    const float* x  = (const float*)d_in[0];   // (65536, 256) f32
    const float* cb = (const float*)d_in[1];   // (4096, 256)  f32
    float* out = (float*)d_out;

    int warps = NPTS + KCB;                    // one warp per row
    prep_kernel<<<(warps * 32 + 255) / 256, 256>>>(x, cb);

    cudaFuncSetAttribute(vq_mma_kernel,
                         cudaFuncAttributeMaxDynamicSharedMemorySize, SMEM_TOTAL);
    vq_mma_kernel<<<148, NTHREADS, SMEM_TOTAL>>>();

    rescore_kernel<<<NPTS / 8, 256>>>(x, cb, out);
}